// round 7
// baseline (speedup 1.0000x reference)
#include <cuda_runtime.h>
#include <cstdint>

// YOLO loss [4096,14,14,30] fp32 x2 -> scalar. 192.7 MB compulsory read.
// Persistent 1-CTA/SM, 3-stage pipeline filled by cp.async.cg (LDGSTS) from
// ALL 256 threads -> deep per-SM MLP via LSU streams instead of the single
// per-SM TMA bulk engine (which capped at ~19 B/cyc/SM in R3-R6).

#define FEAT 30
#define BATCH 4096
#define NCELL (BATCH * 14 * 14)        // 802816
#define TILE 256                       // cells per tile
#define NTILES (NCELL / TILE)          // 3136 exact
#define TPB 256
#define GRID 152                       // 1 CTA/SM (GB300: 152 SMs)
#define STAGES 3
#define TILE_BYTES (TILE * FEAT * 4)   // 30720 per tensor
#define STAGE_BYTES (2 * TILE_BYTES)   // 61440
#define CHUNKS (STAGE_BYTES / (TPB * 16))   // 15 x 16B per thread per stage
#define SMEM_TOTAL (STAGES * STAGE_BYTES)   // 184320

__device__ float g_partials[GRID];
__device__ unsigned int g_done = 0;

__device__ __forceinline__ uint32_t smem_u32(const void* p) {
    uint32_t a;
    asm("{ .reg .u64 t; cvta.to.shared.u64 t, %1; cvt.u32.u64 %0, t; }"
        : "=r"(a) : "l"(p));
    return a;
}

__device__ __forceinline__ void cp16(uint32_t dst, const void* src) {
    asm volatile("cp.async.cg.shared.global [%0], [%1], 16;"
                 :: "r"(dst), "l"(src) : "memory");
}

__device__ __forceinline__ float iou_box(float ax, float ay, float aw, float ah,
                                         float bx, float by, float bw, float bh) {
    float a_x1 = ax - aw * 0.5f, a_y1 = ay - ah * 0.5f;
    float a_x2 = ax + aw * 0.5f, a_y2 = ay + ah * 0.5f;
    float b_x1 = bx - bw * 0.5f, b_y1 = by - bh * 0.5f;
    float b_x2 = bx + bw * 0.5f, b_y2 = by + bh * 0.5f;
    float iw = fmaxf(fminf(a_x2, b_x2) - fmaxf(a_x1, b_x1), 0.0f);
    float ih = fmaxf(fminf(a_y2, b_y2) - fmaxf(a_y1, b_y1), 0.0f);
    float inter = iw * ih;
    float a1 = (a_x2 - a_x1) * (a_y2 - a_y1);
    float a2 = (b_x2 - b_x1) * (b_y2 - b_y1);
    return inter / (a1 + a2 - inter + 1e-6f);
}

__global__ void __launch_bounds__(TPB)
yolo_cpasync_kernel(const float* __restrict__ pred, const float* __restrict__ tgt,
                    float* __restrict__ out) {
    extern __shared__ char smem[];
    const uint32_t smem_base = smem_u32(smem);
    const int tid = threadIdx.x;

    __shared__ float warp_sums[TPB / 32];
    __shared__ bool s_last;

    // issue one stage fill (all threads participate); always commits a group
    auto issue = [&](int tile, int st) {
        if (tile < NTILES) {
            const char* psrc = (const char*)pred + (size_t)tile * TILE_BYTES;
            const char* tsrc = (const char*)tgt  + (size_t)tile * TILE_BYTES;
            uint32_t sbase = smem_base + st * STAGE_BYTES;
#pragma unroll
            for (int k = 0; k < CHUNKS; k++) {
                int off = (tid + k * TPB) * 16;
                const char* src = (off < TILE_BYTES) ? (psrc + off)
                                                     : (tsrc + (off - TILE_BYTES));
                cp16(sbase + off, src);
            }
        }
        asm volatile("cp.async.commit_group;" ::: "memory");
    };

    // ---- prologue: fill all stages ----
#pragma unroll
    for (int s = 0; s < STAGES; s++)
        issue((int)blockIdx.x + s * GRID, s);

    float acc = 0.0f;
    int it = 0;
    for (int tile = blockIdx.x; tile < NTILES; tile += GRID, it++) {
        const int st = it % STAGES;
        asm volatile("cp.async.wait_group %0;" :: "n"(STAGES - 1) : "memory");
        __syncthreads();   // make all threads' async fills visible to all

        const char* buf = smem + st * STAGE_BYTES;
        const float2* P2 = reinterpret_cast<const float2*>(buf + tid * (FEAT * 4));
        const float2* T2 = reinterpret_cast<const float2*>(buf + TILE_BYTES + tid * (FEAT * 4));

        float p[FEAT], t[FEAT];
#pragma unroll
        for (int i = 0; i < FEAT / 2; i++) {
            float2 v = P2[i]; p[2 * i] = v.x; p[2 * i + 1] = v.y;
        }
#pragma unroll
        for (int i = 0; i < FEAT / 2; i++) {
            float2 v = T2[i]; t[2 * i] = v.x; t[2 * i + 1] = v.y;
        }

        // stage fully read -> refill it; flops overlap the refill
        __syncthreads();
        issue(tile + STAGES * GRID, st);

        bool m = t[4] > 0.0f;
        float mf = m ? 1.0f : 0.0f;

        float ce0 = p[4] - t[4]; ce0 *= ce0;
        float ce1 = p[9] - t[9]; ce1 *= ce1;
        float noobj_conf = m ? 0.0f : (ce0 + ce1);

        float iou0 = iou_box(p[0], p[1], p[2], p[3], t[0], t[1], t[2], t[3]);
        float iou1 = iou_box(p[5], p[6], p[7], p[8], t[5], t[6], t[7], t[8]);
        bool best1 = iou1 > iou0;

        float pb0 = best1 ? p[5] : p[0];
        float pb1 = best1 ? p[6] : p[1];
        float pb2 = best1 ? p[7] : p[2];
        float pb3 = best1 ? p[8] : p[3];
        float pb4 = best1 ? p[9] : p[4];
        float tb0 = best1 ? t[5] : t[0];
        float tb1 = best1 ? t[6] : t[1];
        float tb2 = best1 ? t[7] : t[2];
        float tb3 = best1 ? t[8] : t[3];
        float tb4 = best1 ? t[9] : t[4];

        float dx = pb0 - tb0, dy = pb1 - tb1;
        float xy_loss = dx * dx + dy * dy;

        float pw = sqrtf(fabsf(pb2) + 1e-6f);
        float phh = sqrtf(fabsf(pb3) + 1e-6f);
        float tw = sqrtf(m ? tb2 : 1.0f);
        float th = sqrtf(m ? tb3 : 1.0f);
        float dw = pw - tw, dh = phh - th;
        float wh_loss = dw * dw + dh * dh;

        float dobj = pb4 - tb4;
        float nonbest = p[4] + p[9] - pb4;

        float cls = 0.0f;
#pragma unroll
        for (int c = 0; c < 20; c++) {
            float d = p[10 + c] - t[10 + c];
            cls += d * d;
        }

        acc += 5.0f * mf * (xy_loss + wh_loss)
             + mf * dobj * dobj
             + 0.5f * (noobj_conf + 0.5f * mf * nonbest * nonbest)
             + mf * cls;
    }

    // ---- block reduction ----
#pragma unroll
    for (int off = 16; off > 0; off >>= 1)
        acc += __shfl_down_sync(0xFFFFFFFFu, acc, off);
    int lane = tid & 31;
    int wid  = tid >> 5;
    if (lane == 0) warp_sums[wid] = acc;
    __syncthreads();
    if (tid == 0) {
        float v = 0.0f;
#pragma unroll
        for (int w = 0; w < TPB / 32; w++) v += warp_sums[w];
        g_partials[blockIdx.x] = v;
        __threadfence();
        unsigned int done = atomicAdd(&g_done, 1u);
        s_last = (done == (unsigned)(gridDim.x - 1));
    }
    __syncthreads();

    if (s_last) {
        __threadfence();
        float v = 0.0f;
        for (int i = tid; i < GRID; i += TPB)
            v += g_partials[i];
#pragma unroll
        for (int off = 16; off > 0; off >>= 1)
            v += __shfl_down_sync(0xFFFFFFFFu, v, off);
        if (lane == 0) warp_sums[wid] = v;
        __syncthreads();
        if (tid == 0) {
            float tot = 0.0f;
#pragma unroll
            for (int w = 0; w < TPB / 32; w++) tot += warp_sums[w];
            out[0] = tot / (float)BATCH;
            g_done = 0;
        }
    }
}

extern "C" void kernel_launch(void* const* d_in, const int* in_sizes, int n_in,
                              void* d_out, int out_size) {
    const float* pred = (const float*)d_in[0];
    const float* tgt  = (const float*)d_in[1];
    float* out = (float*)d_out;
    cudaFuncSetAttribute(yolo_cpasync_kernel,
                         cudaFuncAttributeMaxDynamicSharedMemorySize, SMEM_TOTAL);
    yolo_cpasync_kernel<<<GRID, TPB, SMEM_TOTAL>>>(pred, tgt, out);
}

// round 8
// speedup vs baseline: 1.0502x; 1.0502x over previous
#include <cuda_runtime.h>
#include <cstdint>

// YOLO loss [4096,14,14,30] fp32 x2 -> scalar. 192.7 MB compulsory read.
// HYBRID: per SM, warps 0-3 run a 3-stage TMA-bulk smem pipeline (tiles
// [0,NT_A)), warps 4-7 run direct strided-LDG compute (tiles [NT_A,NTILES)).
// Two independent memory paths (TMA engine + LSU/L1tex) -> in-flight windows add.

#define FEAT 30
#define BATCH 4096
#define NCELL (BATCH * 14 * 14)        // 802816
#define TILE 256
#define NTILES (NCELL / TILE)          // 3136
#define NT_A 2048                      // tiles via TMA path (65%)
#define CELL0 (NT_A * TILE)            // first LDG-path cell
#define TPB 256
#define GRID 152                       // 1 CTA/SM
#define STAGES 3
#define TILE_BYTES (TILE * FEAT * 4)   // 30720
#define STAGE_BYTES (2 * TILE_BYTES)   // 61440
#define SMEM_BUF_OFF 1024
#define SMEM_TOTAL (SMEM_BUF_OFF + STAGES * STAGE_BYTES)

__device__ float g_partials[GRID];
__device__ unsigned int g_done = 0;

__device__ __forceinline__ uint32_t smem_u32(const void* p) {
    uint32_t a;
    asm("{ .reg .u64 t; cvta.to.shared.u64 t, %1; cvt.u32.u64 %0, t; }"
        : "=r"(a) : "l"(p));
    return a;
}

__device__ __forceinline__ void mbar_init(uint32_t mbar, uint32_t count) {
    asm volatile("mbarrier.init.shared.b64 [%0], %1;" :: "r"(mbar), "r"(count) : "memory");
}

__device__ __forceinline__ void mbar_expect_tx(uint32_t mbar, uint32_t bytes) {
    asm volatile("mbarrier.arrive.expect_tx.shared.b64 _, [%0], %1;"
                 :: "r"(mbar), "r"(bytes) : "memory");
}

__device__ __forceinline__ void mbar_wait(uint32_t mbar, uint32_t phase) {
    asm volatile(
        "{\n\t"
        ".reg .pred P1;\n\t"
        "WAIT_LOOP_%=:\n\t"
        "mbarrier.try_wait.parity.acquire.cta.shared::cta.b64 P1, [%0], %1, 0x989680;\n\t"
        "@P1 bra.uni WAIT_DONE_%=;\n\t"
        "bra.uni WAIT_LOOP_%=;\n\t"
        "WAIT_DONE_%=:\n\t"
        "}"
        :: "r"(mbar), "r"(phase) : "memory");
}

__device__ __forceinline__ void bulk_g2s(uint32_t dst, const void* src,
                                         uint32_t bytes, uint32_t mbar) {
    asm volatile(
        "cp.async.bulk.shared::cluster.global.mbarrier::complete_tx::bytes "
        "[%0], [%1], %2, [%3];"
        :: "r"(dst), "l"(src), "r"(bytes), "r"(mbar) : "memory");
}

__device__ __forceinline__ float iou_box(float ax, float ay, float aw, float ah,
                                         float bx, float by, float bw, float bh) {
    float a_x1 = ax - aw * 0.5f, a_y1 = ay - ah * 0.5f;
    float a_x2 = ax + aw * 0.5f, a_y2 = ay + ah * 0.5f;
    float b_x1 = bx - bw * 0.5f, b_y1 = by - bh * 0.5f;
    float b_x2 = bx + bw * 0.5f, b_y2 = by + bh * 0.5f;
    float iw = fmaxf(fminf(a_x2, b_x2) - fmaxf(a_x1, b_x1), 0.0f);
    float ih = fmaxf(fminf(a_y2, b_y2) - fmaxf(a_y1, b_y1), 0.0f);
    float inter = iw * ih;
    float a1 = (a_x2 - a_x1) * (a_y2 - a_y1);
    float a2 = (b_x2 - b_x1) * (b_y2 - b_y1);
    return inter / (a1 + a2 - inter + 1e-6f);
}

// full per-cell loss; all indices constant -> stays in registers
__device__ __forceinline__ float cell_loss(const float* p, const float* t) {
    bool m = t[4] > 0.0f;
    float mf = m ? 1.0f : 0.0f;

    float ce0 = p[4] - t[4]; ce0 *= ce0;
    float ce1 = p[9] - t[9]; ce1 *= ce1;
    float noobj_conf = m ? 0.0f : (ce0 + ce1);

    float iou0 = iou_box(p[0], p[1], p[2], p[3], t[0], t[1], t[2], t[3]);
    float iou1 = iou_box(p[5], p[6], p[7], p[8], t[5], t[6], t[7], t[8]);
    bool best1 = iou1 > iou0;

    float pb0 = best1 ? p[5] : p[0];
    float pb1 = best1 ? p[6] : p[1];
    float pb2 = best1 ? p[7] : p[2];
    float pb3 = best1 ? p[8] : p[3];
    float pb4 = best1 ? p[9] : p[4];
    float tb0 = best1 ? t[5] : t[0];
    float tb1 = best1 ? t[6] : t[1];
    float tb2 = best1 ? t[7] : t[2];
    float tb3 = best1 ? t[8] : t[3];
    float tb4 = best1 ? t[9] : t[4];

    float dx = pb0 - tb0, dy = pb1 - tb1;
    float xy_loss = dx * dx + dy * dy;

    float pw = sqrtf(fabsf(pb2) + 1e-6f);
    float phh = sqrtf(fabsf(pb3) + 1e-6f);
    float tw = sqrtf(m ? tb2 : 1.0f);
    float th = sqrtf(m ? tb3 : 1.0f);
    float dw = pw - tw, dh = phh - th;
    float wh_loss = dw * dw + dh * dh;

    float dobj = pb4 - tb4;
    float nonbest = p[4] + p[9] - pb4;

    float cls = 0.0f;
#pragma unroll
    for (int c = 0; c < 20; c++) {
        float d = p[10 + c] - t[10 + c];
        cls += d * d;
    }

    return 5.0f * mf * (xy_loss + wh_loss)
         + mf * dobj * dobj
         + 0.5f * (noobj_conf + 0.5f * mf * nonbest * nonbest)
         + mf * cls;
}

__global__ void __launch_bounds__(TPB)
yolo_hybrid_kernel(const float* __restrict__ pred, const float* __restrict__ tgt,
                   float* __restrict__ out) {
    extern __shared__ char smem[];
    const uint32_t smem_base = smem_u32(smem);
    const int tid = threadIdx.x;

    __shared__ float warp_sums[TPB / 32];
    __shared__ bool s_last;

    if (tid == 0) {
#pragma unroll
        for (int s = 0; s < STAGES; s++)
            mbar_init(smem_base + s * 8, 1);
        asm volatile("fence.proxy.async.shared::cta;" ::: "memory");
    }
    __syncthreads();

    float acc = 0.0f;

    if (tid < 128) {
        // ================= TMA half: tiles [0, NT_A) =================
        if (tid == 0) {
#pragma unroll
            for (int s = 0; s < STAGES; s++) {
                int tt = (int)blockIdx.x + s * GRID;
                if (tt < NT_A) {
                    uint32_t mbar = smem_base + s * 8;
                    uint32_t dst = smem_base + SMEM_BUF_OFF + s * STAGE_BYTES;
                    mbar_expect_tx(mbar, STAGE_BYTES);
                    bulk_g2s(dst, (const char*)pred + (size_t)tt * TILE_BYTES, TILE_BYTES, mbar);
                    bulk_g2s(dst + TILE_BYTES, (const char*)tgt + (size_t)tt * TILE_BYTES, TILE_BYTES, mbar);
                }
            }
        }

        int it = 0;
        for (int tile = blockIdx.x; tile < NT_A; tile += GRID, it++) {
            const int st = it % STAGES;
            const uint32_t ph = (uint32_t)(it / STAGES) & 1u;
            mbar_wait(smem_base + st * 8, ph);

            const char* buf = smem + SMEM_BUF_OFF + st * STAGE_BYTES;

            // each of 128 threads handles 2 cells of the 256-cell tile
            float l2sum = 0.0f;
#pragma unroll
            for (int half = 0; half < 2; half++) {
                int cell = tid + half * 128;
                const float2* P2 = reinterpret_cast<const float2*>(buf + cell * (FEAT * 4));
                const float2* T2 = reinterpret_cast<const float2*>(buf + TILE_BYTES + cell * (FEAT * 4));
                float p[FEAT], t[FEAT];
#pragma unroll
                for (int i = 0; i < FEAT / 2; i++) {
                    float2 v = P2[i]; p[2 * i] = v.x; p[2 * i + 1] = v.y;
                }
#pragma unroll
                for (int i = 0; i < FEAT / 2; i++) {
                    float2 v = T2[i]; t[2 * i] = v.x; t[2 * i + 1] = v.y;
                }
                l2sum += cell_loss(p, t);
            }

            // all 128 consumers done with this stage -> refill
            asm volatile("bar.sync 1, 128;" ::: "memory");
            if (tid == 0) {
                int tt = tile + STAGES * GRID;
                if (tt < NT_A) {
                    uint32_t mbar = smem_base + st * 8;
                    uint32_t dst = smem_base + SMEM_BUF_OFF + st * STAGE_BYTES;
                    mbar_expect_tx(mbar, STAGE_BYTES);
                    bulk_g2s(dst, (const char*)pred + (size_t)tt * TILE_BYTES, TILE_BYTES, mbar);
                    bulk_g2s(dst + TILE_BYTES, (const char*)tgt + (size_t)tt * TILE_BYTES, TILE_BYTES, mbar);
                }
            }
            acc += l2sum;
        }
    } else {
        // ================= LDG half: cells [CELL0, NCELL) =================
        const int gtid = (int)blockIdx.x * 128 + (tid - 128);
        const int stride = GRID * 128;
        for (int c = CELL0 + gtid; c < NCELL; c += stride) {
            const float2* P2 = reinterpret_cast<const float2*>(pred + (size_t)c * FEAT);
            const float2* T2 = reinterpret_cast<const float2*>(tgt  + (size_t)c * FEAT);
            float p[FEAT], t[FEAT];
#pragma unroll
            for (int i = 0; i < FEAT / 2; i++) {
                float2 v = P2[i]; p[2 * i] = v.x; p[2 * i + 1] = v.y;
            }
#pragma unroll
            for (int i = 0; i < FEAT / 2; i++) {
                float2 v = T2[i]; t[2 * i] = v.x; t[2 * i + 1] = v.y;
            }
            acc += cell_loss(p, t);
        }
    }

    // ---- block reduction (both halves) ----
#pragma unroll
    for (int off = 16; off > 0; off >>= 1)
        acc += __shfl_down_sync(0xFFFFFFFFu, acc, off);
    int lane = tid & 31;
    int wid  = tid >> 5;
    if (lane == 0) warp_sums[wid] = acc;
    __syncthreads();
    if (tid == 0) {
        float v = 0.0f;
#pragma unroll
        for (int w = 0; w < TPB / 32; w++) v += warp_sums[w];
        g_partials[blockIdx.x] = v;
        __threadfence();
        unsigned int done = atomicAdd(&g_done, 1u);
        s_last = (done == (unsigned)(gridDim.x - 1));
    }
    __syncthreads();

    if (s_last) {
        __threadfence();
        float v = 0.0f;
        for (int i = tid; i < GRID; i += TPB)
            v += g_partials[i];
#pragma unroll
        for (int off = 16; off > 0; off >>= 1)
            v += __shfl_down_sync(0xFFFFFFFFu, v, off);
        if (lane == 0) warp_sums[wid] = v;
        __syncthreads();
        if (tid == 0) {
            float tot = 0.0f;
#pragma unroll
            for (int w = 0; w < TPB / 32; w++) tot += warp_sums[w];
            out[0] = tot / (float)BATCH;
            g_done = 0;
        }
    }
}

extern "C" void kernel_launch(void* const* d_in, const int* in_sizes, int n_in,
                              void* d_out, int out_size) {
    const float* pred = (const float*)d_in[0];
    const float* tgt  = (const float*)d_in[1];
    float* out = (float*)d_out;
    cudaFuncSetAttribute(yolo_hybrid_kernel,
                         cudaFuncAttributeMaxDynamicSharedMemorySize, SMEM_TOTAL);
    yolo_hybrid_kernel<<<GRID, TPB, SMEM_TOTAL>>>(pred, tgt, out);
}

// round 9
// speedup vs baseline: 1.1940x; 1.1370x over previous
#include <cuda_runtime.h>
#include <cstdint>

// YOLO loss [4096,14,14,30] fp32 x2 -> scalar. 192.7 MB compulsory read.
// Persistent 1-CTA/SM, 448 threads (14 warps) to hide consumer latency,
// 2-stage cp.async.bulk pipeline (210KB smem), dynamic tile tickets.

#define FEAT 30
#define BATCH 4096
#define NCELL (BATCH * 14 * 14)        // 802816
#define TILE 448                       // cells per tile; 802816 = 448*1792
#define NTILES (NCELL / TILE)          // 1792 exact
#define TPB 448                        // 14 warps
#define GRID 152                       // 1 CTA/SM
#define STAGES 2
#define TILE_BYTES (TILE * FEAT * 4)   // 53760 per tensor
#define STAGE_BYTES (2 * TILE_BYTES)   // 107520
#define SMEM_BUF_OFF 1024
#define SMEM_TOTAL (SMEM_BUF_OFF + STAGES * STAGE_BYTES)   // 216064 <= 227KB

__device__ float g_partials[GRID];
__device__ unsigned int g_done = 0;
__device__ unsigned int g_next = 0;

__device__ __forceinline__ uint32_t smem_u32(const void* p) {
    uint32_t a;
    asm("{ .reg .u64 t; cvta.to.shared.u64 t, %1; cvt.u32.u64 %0, t; }"
        : "=r"(a) : "l"(p));
    return a;
}

__device__ __forceinline__ void mbar_init(uint32_t mbar, uint32_t count) {
    asm volatile("mbarrier.init.shared.b64 [%0], %1;" :: "r"(mbar), "r"(count) : "memory");
}

__device__ __forceinline__ void mbar_expect_tx(uint32_t mbar, uint32_t bytes) {
    asm volatile("mbarrier.arrive.expect_tx.shared.b64 _, [%0], %1;"
                 :: "r"(mbar), "r"(bytes) : "memory");
}

__device__ __forceinline__ void mbar_arrive(uint32_t mbar) {
    asm volatile("mbarrier.arrive.release.cta.shared::cta.b64 _, [%0];"
                 :: "r"(mbar) : "memory");
}

__device__ __forceinline__ void mbar_wait(uint32_t mbar, uint32_t phase) {
    asm volatile(
        "{\n\t"
        ".reg .pred P1;\n\t"
        "WAIT_LOOP_%=:\n\t"
        "mbarrier.try_wait.parity.acquire.cta.shared::cta.b64 P1, [%0], %1, 0x989680;\n\t"
        "@P1 bra.uni WAIT_DONE_%=;\n\t"
        "bra.uni WAIT_LOOP_%=;\n\t"
        "WAIT_DONE_%=:\n\t"
        "}"
        :: "r"(mbar), "r"(phase) : "memory");
}

__device__ __forceinline__ void bulk_g2s(uint32_t dst, const void* src,
                                         uint32_t bytes, uint32_t mbar) {
    asm volatile(
        "cp.async.bulk.shared::cluster.global.mbarrier::complete_tx::bytes "
        "[%0], [%1], %2, [%3];"
        :: "r"(dst), "l"(src), "r"(bytes), "r"(mbar) : "memory");
}

__device__ __forceinline__ float iou_box(float ax, float ay, float aw, float ah,
                                         float bx, float by, float bw, float bh) {
    float a_x1 = ax - aw * 0.5f, a_y1 = ay - ah * 0.5f;
    float a_x2 = ax + aw * 0.5f, a_y2 = ay + ah * 0.5f;
    float b_x1 = bx - bw * 0.5f, b_y1 = by - bh * 0.5f;
    float b_x2 = bx + bw * 0.5f, b_y2 = by + bh * 0.5f;
    float iw = fmaxf(fminf(a_x2, b_x2) - fmaxf(a_x1, b_x1), 0.0f);
    float ih = fmaxf(fminf(a_y2, b_y2) - fmaxf(a_y1, b_y1), 0.0f);
    float inter = iw * ih;
    float a1 = (a_x2 - a_x1) * (a_y2 - a_y1);
    float a2 = (b_x2 - b_x1) * (b_y2 - b_y1);
    return inter / (a1 + a2 - inter + 1e-6f);
}

__device__ __forceinline__ float cell_loss(const float* p, const float* t) {
    bool m = t[4] > 0.0f;
    float mf = m ? 1.0f : 0.0f;

    float ce0 = p[4] - t[4]; ce0 *= ce0;
    float ce1 = p[9] - t[9]; ce1 *= ce1;
    float noobj_conf = m ? 0.0f : (ce0 + ce1);

    float iou0 = iou_box(p[0], p[1], p[2], p[3], t[0], t[1], t[2], t[3]);
    float iou1 = iou_box(p[5], p[6], p[7], p[8], t[5], t[6], t[7], t[8]);
    bool best1 = iou1 > iou0;

    float pb0 = best1 ? p[5] : p[0];
    float pb1 = best1 ? p[6] : p[1];
    float pb2 = best1 ? p[7] : p[2];
    float pb3 = best1 ? p[8] : p[3];
    float pb4 = best1 ? p[9] : p[4];
    float tb0 = best1 ? t[5] : t[0];
    float tb1 = best1 ? t[6] : t[1];
    float tb2 = best1 ? t[7] : t[2];
    float tb3 = best1 ? t[8] : t[3];
    float tb4 = best1 ? t[9] : t[4];

    float dx = pb0 - tb0, dy = pb1 - tb1;
    float xy_loss = dx * dx + dy * dy;

    float pw = sqrtf(fabsf(pb2) + 1e-6f);
    float phh = sqrtf(fabsf(pb3) + 1e-6f);
    float tw = sqrtf(m ? tb2 : 1.0f);
    float th = sqrtf(m ? tb3 : 1.0f);
    float dw = pw - tw, dh = phh - th;
    float wh_loss = dw * dw + dh * dh;

    float dobj = pb4 - tb4;
    float nonbest = p[4] + p[9] - pb4;

    float cls = 0.0f;
#pragma unroll
    for (int c = 0; c < 20; c++) {
        float d = p[10 + c] - t[10 + c];
        cls += d * d;
    }

    return 5.0f * mf * (xy_loss + wh_loss)
         + mf * dobj * dobj
         + 0.5f * (noobj_conf + 0.5f * mf * nonbest * nonbest)
         + mf * cls;
}

__global__ void __launch_bounds__(TPB)
yolo_wide_kernel(const float* __restrict__ pred, const float* __restrict__ tgt,
                 float* __restrict__ out) {
    extern __shared__ char smem[];
    const uint32_t smem_base = smem_u32(smem);
    const int tid = threadIdx.x;

    __shared__ int s_tile[STAGES];
    __shared__ float warp_sums[TPB / 32];
    __shared__ bool s_last;

    if (tid == 0) {
#pragma unroll
        for (int s = 0; s < STAGES; s++)
            mbar_init(smem_base + s * 8, 1);
        asm volatile("fence.proxy.async.shared::cta;" ::: "memory");
    }
    __syncthreads();

    auto issue_next = [&](int s) {
        unsigned int tt = atomicAdd(&g_next, 1u);
        uint32_t mbar = smem_base + s * 8;
        if (tt < NTILES) {
            s_tile[s] = (int)tt;
            uint32_t dst = smem_base + SMEM_BUF_OFF + s * STAGE_BYTES;
            mbar_expect_tx(mbar, STAGE_BYTES);
            bulk_g2s(dst, (const char*)pred + (size_t)tt * TILE_BYTES, TILE_BYTES, mbar);
            bulk_g2s(dst + TILE_BYTES, (const char*)tgt + (size_t)tt * TILE_BYTES, TILE_BYTES, mbar);
        } else {
            s_tile[s] = -1;
            mbar_arrive(mbar);
        }
    };

    if (tid == 0) {
#pragma unroll
        for (int s = 0; s < STAGES; s++)
            issue_next(s);
    }

    float acc = 0.0f;
    for (int it = 0;; it++) {
        const int st = it % STAGES;
        const uint32_t ph = (uint32_t)(it / STAGES) & 1u;
        mbar_wait(smem_base + st * 8, ph);

        if (s_tile[st] < 0) break;

        const char* buf = smem + SMEM_BUF_OFF + st * STAGE_BYTES;
        const float2* P2 = reinterpret_cast<const float2*>(buf + tid * (FEAT * 4));
        const float2* T2 = reinterpret_cast<const float2*>(buf + TILE_BYTES + tid * (FEAT * 4));

        float p[FEAT], t[FEAT];
#pragma unroll
        for (int i = 0; i < FEAT / 2; i++) {
            float2 v = P2[i]; p[2 * i] = v.x; p[2 * i + 1] = v.y;
        }
#pragma unroll
        for (int i = 0; i < FEAT / 2; i++) {
            float2 v = T2[i]; t[2 * i] = v.x; t[2 * i + 1] = v.y;
        }

        // stage fully read -> refill ASAP; flops overlap the refill
        __syncthreads();
        if (tid == 0)
            issue_next(st);

        acc += cell_loss(p, t);
    }

    // ---- block reduction ----
#pragma unroll
    for (int off = 16; off > 0; off >>= 1)
        acc += __shfl_down_sync(0xFFFFFFFFu, acc, off);
    int lane = tid & 31;
    int wid  = tid >> 5;
    if (lane == 0) warp_sums[wid] = acc;
    __syncthreads();
    if (tid == 0) {
        float v = 0.0f;
#pragma unroll
        for (int w = 0; w < TPB / 32; w++) v += warp_sums[w];
        g_partials[blockIdx.x] = v;
        __threadfence();
        unsigned int done = atomicAdd(&g_done, 1u);
        s_last = (done == (unsigned)(gridDim.x - 1));
    }
    __syncthreads();

    if (s_last) {
        __threadfence();
        float v = 0.0f;
        for (int i = tid; i < GRID; i += TPB)
            v += g_partials[i];
#pragma unroll
        for (int off = 16; off > 0; off >>= 1)
            v += __shfl_down_sync(0xFFFFFFFFu, v, off);
        if (lane == 0) warp_sums[wid] = v;
        __syncthreads();
        if (tid == 0) {
            float tot = 0.0f;
#pragma unroll
            for (int w = 0; w < TPB / 32; w++) tot += warp_sums[w];
            out[0] = tot / (float)BATCH;
            g_next = 0;
            g_done = 0;
        }
    }
}

extern "C" void kernel_launch(void* const* d_in, const int* in_sizes, int n_in,
                              void* d_out, int out_size) {
    const float* pred = (const float*)d_in[0];
    const float* tgt  = (const float*)d_in[1];
    float* out = (float*)d_out;
    cudaFuncSetAttribute(yolo_wide_kernel,
                         cudaFuncAttributeMaxDynamicSharedMemorySize, SMEM_TOTAL);
    yolo_wide_kernel<<<GRID, TPB, SMEM_TOTAL>>>(pred, tgt, out);
}